// round 3
// baseline (speedup 1.0000x reference)
#include <cuda_runtime.h>
#include <math.h>

// Dataset-fixed shapes: r is [16, 2048, 3] fp32
#define BATCH   16
#define NCC     2
#define NPTS    1024              // points per MST problem
#define NPROB   (BATCH * NCC)     // 32 independent MST problems
#define THREADS 256
#define PPT     (NPTS / THREADS)  // 4 points per thread
#define NW      (THREADS / 32)    // 8 warps

__device__ float    g_partials[NPROB];
__device__ unsigned g_ticket;     // zero-initialized; last CTA resets it

__device__ __forceinline__ float warp_sum(float v) {
#pragma unroll
    for (int o = 16; o; o >>= 1) v += __shfl_xor_sync(0xffffffffu, v, o);
    return v;
}

__device__ __forceinline__ unsigned um(unsigned a, unsigned b) { return a < b ? a : b; }

// Pack: high 22 bits = float bits of squared distance (low 10 mantissa bits
// truncated), low 10 bits = point index. Unsigned order == (dist, idx) order.
// All pk values are globally UNIQUE (index embedded), so argmin is unambiguous.
#define PK_MASK 0xFFFFFC00u

__global__ __launch_bounds__(THREADS, 1)
void topo_mst_kernel(const float* __restrict__ r, float* __restrict__ out)
{
    __shared__ float redbuf[3][NW];
    __shared__ float s_p0[3];
    __shared__ alignas(16) float4 s_win[2][NW];  // double-buffered {x,y,z,packed}
    __shared__ bool s_last;

    const int prob   = blockIdx.x;
    const int sample = prob >> 1;
    const int chunk  = prob & 1;
    const int tid    = threadIdx.x;
    const int lane   = tid & 31;
    const int wid    = tid >> 5;

    const float* base = r + ((size_t)sample * (NCC * NPTS) + (size_t)chunk * NPTS) * 3;

    // ---- Load (thread t owns points t, t+256, t+512, t+768) ----
    float lx[PPT], ly[PPT], lz[PPT];
    float sx = 0.f, sy = 0.f, sz = 0.f;
#pragma unroll
    for (int s = 0; s < PPT; s++) {
        int i = tid + s * THREADS;
        float x = base[3 * i + 0];
        float y = base[3 * i + 1];
        float z = base[3 * i + 2];
        lx[s] = x; ly[s] = y; lz[s] = z;
        sx += x; sy += y; sz += z;
    }

    // ---- Mean ----
    sx = warp_sum(sx); sy = warp_sum(sy); sz = warp_sum(sz);
    if (lane == 0) { redbuf[0][wid] = sx; redbuf[1][wid] = sy; redbuf[2][wid] = sz; }
    __syncthreads();
    float mx = 0.f, my = 0.f, mz = 0.f;
#pragma unroll
    for (int w = 0; w < NW; w++) { mx += redbuf[0][w]; my += redbuf[1][w]; mz += redbuf[2][w]; }
    mx *= (1.0f / NPTS); my *= (1.0f / NPTS); mz *= (1.0f / NPTS);
    __syncthreads();

    // ---- Variance ----
    float vx = 0.f, vy = 0.f, vz = 0.f;
#pragma unroll
    for (int s = 0; s < PPT; s++) {
        float dx = lx[s] - mx, dy = ly[s] - my, dz = lz[s] - mz;
        vx = fmaf(dx, dx, vx); vy = fmaf(dy, dy, vy); vz = fmaf(dz, dz, vz);
    }
    vx = warp_sum(vx); vy = warp_sum(vy); vz = warp_sum(vz);
    if (lane == 0) { redbuf[0][wid] = vx; redbuf[1][wid] = vy; redbuf[2][wid] = vz; }
    __syncthreads();
    vx = 0.f; vy = 0.f; vz = 0.f;
#pragma unroll
    for (int w = 0; w < NW; w++) { vx += redbuf[0][w]; vy += redbuf[1][w]; vz += redbuf[2][w]; }
    const float inx = 1.0f / (sqrtf(vx * (1.0f / NPTS)) + 1e-8f);
    const float iny = 1.0f / (sqrtf(vy * (1.0f / NPTS)) + 1e-8f);
    const float inz = 1.0f / (sqrtf(vz * (1.0f / NPTS)) + 1e-8f);

    // ---- Normalize into registers; broadcast point 0 ----
#pragma unroll
    for (int s = 0; s < PPT; s++) {
        lx[s] = (lx[s] - mx) * inx;
        ly[s] = (ly[s] - my) * iny;
        lz[s] = (lz[s] - mz) * inz;
    }
    if (tid == 0) { s_p0[0] = lx[0]; s_p0[1] = ly[0]; s_p0[2] = lz[0]; }
    __syncthreads();

    // ---- Prim's MST ----
    const float    INF_F   = __int_as_float(0x7f800000);
    const unsigned VISITED = 0xFFFFFFFFu;

    const float x0 = s_p0[0], y0 = s_p0[1], z0 = s_p0[2];
    unsigned pk[PPT];
#pragma unroll
    for (int s = 0; s < PPT; s++) {
        float dx = lx[s] - x0, dy = ly[s] - y0, dz = lz[s] - z0;
        float d2 = fmaf(dx, dx, fmaf(dy, dy, dz * dz));
        pk[s] = (__float_as_uint(d2) & PK_MASK) | (unsigned)(tid + s * THREADS);
    }
    if (tid == 0) {     // root is visited; INF coords make its future d2 = +inf
        pk[0] = VISITED;
        lx[0] = INF_F; ly[0] = INF_F; lz[0] = INF_F;
    }

    float total = 0.0f;
    for (int it = 0; it < NPTS - 1; ++it) {
        const int buf = it & 1;

        // ---- thread-local argmin WITH coords (SEL tree, hides under REDUX) ----
        bool q01 = pk[1] < pk[0];
        unsigned m01 = q01 ? pk[1] : pk[0];
        float x01 = q01 ? lx[1] : lx[0];
        float y01 = q01 ? ly[1] : ly[0];
        float z01 = q01 ? lz[1] : lz[0];
        bool q23 = pk[3] < pk[2];
        unsigned m23 = q23 ? pk[3] : pk[2];
        float x23 = q23 ? lx[3] : lx[2];
        float y23 = q23 ? ly[3] : ly[2];
        float z23 = q23 ? lz[3] : lz[2];
        bool qf = m23 < m01;
        unsigned lm = qf ? m23 : m01;
        float cx = qf ? x23 : x01;
        float cy = qf ? y23 : y01;
        float cz = qf ? z23 : z01;

        unsigned wm = __reduce_min_sync(0xffffffffu, lm);
        // exactly one lane matches (pk values unique); it ships min AND coords
        if (lm == wm) s_win[buf][wid] = make_float4(cx, cy, cz, __uint_as_float(wm));
        __syncthreads();   // one barrier per iteration (double-buffered exchange)

        // ---- cross-warp tournament: 8 independent LDS.128 + 3-level SEL ----
        float4 a0 = s_win[buf][0], a1 = s_win[buf][1];
        float4 a2 = s_win[buf][2], a3 = s_win[buf][3];
        float4 a4 = s_win[buf][4], a5 = s_win[buf][5];
        float4 a6 = s_win[buf][6], a7 = s_win[buf][7];
        unsigned u0 = __float_as_uint(a0.w), u1 = __float_as_uint(a1.w);
        unsigned u2 = __float_as_uint(a2.w), u3 = __float_as_uint(a3.w);
        unsigned u4 = __float_as_uint(a4.w), u5 = __float_as_uint(a5.w);
        unsigned u6 = __float_as_uint(a6.w), u7 = __float_as_uint(a7.w);

        bool b0 = u1 < u0;  unsigned v0 = b0 ? u1 : u0;
        float gx0 = b0 ? a1.x : a0.x, gy0 = b0 ? a1.y : a0.y, gz0 = b0 ? a1.z : a0.z;
        bool b1 = u3 < u2;  unsigned v1 = b1 ? u3 : u2;
        float gx1 = b1 ? a3.x : a2.x, gy1 = b1 ? a3.y : a2.y, gz1 = b1 ? a3.z : a2.z;
        bool b2 = u5 < u4;  unsigned v2 = b2 ? u5 : u4;
        float gx2 = b2 ? a5.x : a4.x, gy2 = b2 ? a5.y : a4.y, gz2 = b2 ? a5.z : a4.z;
        bool b3 = u7 < u6;  unsigned v3 = b3 ? u7 : u6;
        float gx3 = b3 ? a7.x : a6.x, gy3 = b3 ? a7.y : a6.y, gz3 = b3 ? a7.z : a6.z;

        bool c0 = v1 < v0;  unsigned w0 = c0 ? v1 : v0;
        float hx0 = c0 ? gx1 : gx0, hy0 = c0 ? gy1 : gy0, hz0 = c0 ? gz1 : gz0;
        bool c1 = v3 < v2;  unsigned w1 = c1 ? v3 : v2;
        float hx1 = c1 ? gx3 : gx2, hy1 = c1 ? gy3 : gy2, hz1 = c1 ? gz3 : gz2;

        bool d0 = w1 < w0;
        unsigned g = d0 ? w1 : w0;
        float gx = d0 ? hx1 : hx0, gy = d0 ? hy1 : hy0, gz = d0 ? hz1 : hz0;

        int gj = (int)(g & 1023u);
        total += __uint_as_float(g & PK_MASK);

        // mark chosen point visited in its owner's registers (off critical path)
#pragma unroll
        for (int s = 0; s < PPT; s++) {
            if (gj == tid + s * THREADS) {
                pk[s] = VISITED;
                lx[s] = INF_F; ly[s] = INF_F; lz[s] = INF_F;
            }
        }

        // relax: INF coords -> d2 = +inf -> packed above every finite value
#pragma unroll
        for (int s = 0; s < PPT; s++) {
            float dx = lx[s] - gx, dy = ly[s] - gy, dz = lz[s] - gz;
            float d2 = fmaf(dx, dx, fmaf(dy, dy, dz * dz));
            unsigned cand = (__float_as_uint(d2) & PK_MASK) | (unsigned)(tid + s * THREADS);
            pk[s] = um(pk[s], cand);
        }
    }

    // ---- deterministic finalize in the last-arriving CTA ----
    if (tid == 0) {
        g_partials[prob] = total;
        __threadfence();
        unsigned t = atomicAdd(&g_ticket, 1u);
        s_last = (t == NPROB - 1);
    }
    __syncthreads();
    if (s_last && tid == 0) {
        __threadfence();
        float acc = 0.0f;
#pragma unroll
        for (int p = 0; p < NPROB; p++) acc += g_partials[p];
        out[0] = acc * (1.0f / NPROB);
        g_ticket = 0;   // reset for next graph replay
    }
}

extern "C" void kernel_launch(void* const* d_in, const int* in_sizes, int n_in,
                              void* d_out, int out_size)
{
    const float* r = (const float*)d_in[0];
    float* out = (float*)d_out;
    topo_mst_kernel<<<NPROB, THREADS>>>(r, out);
}

// round 4
// speedup vs baseline: 2.0377x; 2.0377x over previous
#include <cuda_runtime.h>
#include <math.h>

// Dataset-fixed shapes: r is [16, 2048, 3] fp32
#define BATCH   16
#define NCC     2
#define NPTS    1024              // points per MST problem
#define NPROB   (BATCH * NCC)     // 32 independent MST problems
#define THREADS 128               // 4 warps: ONE warp per SMSP (full issue rate)
#define PPT     (NPTS / THREADS)  // 8 points per thread
#define NW      (THREADS / 32)    // 4 warps

__device__ float    g_partials[NPROB];
__device__ unsigned g_ticket;     // zero-init; last CTA resets for graph replay

__device__ __forceinline__ float warp_sum(float v) {
#pragma unroll
    for (int o = 16; o; o >>= 1) v += __shfl_xor_sync(0xffffffffu, v, o);
    return v;
}

__device__ __forceinline__ unsigned um(unsigned a, unsigned b) { return a < b ? a : b; }

// Pack: high 22 bits = float bits of squared distance (low 10 mantissa bits
// truncated), low 10 bits = point index. Unsigned order == (dist, idx) order.
#define PK_MASK 0xFFFFFC00u

__global__ __launch_bounds__(THREADS, 1)
void topo_mst_kernel(const float* __restrict__ r, float* __restrict__ out)
{
    __shared__ float4 pts[NPTS];                    // normalized points (w unused)
    __shared__ float redbuf[3][NW];
    __shared__ alignas(16) unsigned s_pk[2][NW];    // double-buffered warp mins
    __shared__ bool s_last;

    const int prob   = blockIdx.x;
    const int sample = prob >> 1;
    const int chunk  = prob & 1;
    const int tid    = threadIdx.x;
    const int lane   = tid & 31;
    const int wid    = tid >> 5;

    const float* base = r + ((size_t)sample * (NCC * NPTS) + (size_t)chunk * NPTS) * 3;

    // ---- Load (thread t owns points t, t+128, ..., t+896) ----
    float lx[PPT], ly[PPT], lz[PPT];
    float sx = 0.f, sy = 0.f, sz = 0.f;
#pragma unroll
    for (int s = 0; s < PPT; s++) {
        int i = tid + s * THREADS;
        float x = base[3 * i + 0];
        float y = base[3 * i + 1];
        float z = base[3 * i + 2];
        lx[s] = x; ly[s] = y; lz[s] = z;
        sx += x; sy += y; sz += z;
    }

    // ---- Mean ----
    sx = warp_sum(sx); sy = warp_sum(sy); sz = warp_sum(sz);
    if (lane == 0) { redbuf[0][wid] = sx; redbuf[1][wid] = sy; redbuf[2][wid] = sz; }
    __syncthreads();
    float mx = 0.f, my = 0.f, mz = 0.f;
#pragma unroll
    for (int w = 0; w < NW; w++) { mx += redbuf[0][w]; my += redbuf[1][w]; mz += redbuf[2][w]; }
    mx *= (1.0f / NPTS); my *= (1.0f / NPTS); mz *= (1.0f / NPTS);
    __syncthreads();

    // ---- Variance ----
    float vx = 0.f, vy = 0.f, vz = 0.f;
#pragma unroll
    for (int s = 0; s < PPT; s++) {
        float dx = lx[s] - mx, dy = ly[s] - my, dz = lz[s] - mz;
        vx = fmaf(dx, dx, vx); vy = fmaf(dy, dy, vy); vz = fmaf(dz, dz, vz);
    }
    vx = warp_sum(vx); vy = warp_sum(vy); vz = warp_sum(vz);
    if (lane == 0) { redbuf[0][wid] = vx; redbuf[1][wid] = vy; redbuf[2][wid] = vz; }
    __syncthreads();
    vx = 0.f; vy = 0.f; vz = 0.f;
#pragma unroll
    for (int w = 0; w < NW; w++) { vx += redbuf[0][w]; vy += redbuf[1][w]; vz += redbuf[2][w]; }
    const float inx = 1.0f / (sqrtf(vx * (1.0f / NPTS)) + 1e-8f);
    const float iny = 1.0f / (sqrtf(vy * (1.0f / NPTS)) + 1e-8f);
    const float inz = 1.0f / (sqrtf(vz * (1.0f / NPTS)) + 1e-8f);

    // ---- Normalize into registers + shared float4 broadcast copy ----
#pragma unroll
    for (int s = 0; s < PPT; s++) {
        int i = tid + s * THREADS;
        lx[s] = (lx[s] - mx) * inx;
        ly[s] = (ly[s] - my) * iny;
        lz[s] = (lz[s] - mz) * inz;
        pts[i] = make_float4(lx[s], ly[s], lz[s], 0.0f);
    }
    __syncthreads();

    // ---- Prim's MST ----
    const float    INF_F   = __int_as_float(0x7f800000);
    const unsigned VISITED = 0xFFFFFFFFu;

    float4 p0 = pts[0];
    unsigned pk[PPT];
#pragma unroll
    for (int s = 0; s < PPT; s++) {
        float dx = lx[s] - p0.x, dy = ly[s] - p0.y, dz = lz[s] - p0.z;
        float d2 = fmaf(dx, dx, fmaf(dy, dy, dz * dz));
        pk[s] = (__float_as_uint(d2) & PK_MASK) | (unsigned)(tid + s * THREADS);
    }
    if (tid == 0) {     // root visited; INF x-coord forces its future d2 = +inf
        pk[0] = VISITED;
        lx[0] = INF_F;
    }

    float total = 0.0f;
    for (int it = 0; it < NPTS - 1; ++it) {
        const int buf = it & 1;

        // thread-local min: 7 IMNMX (depth 3); REDUX carries value AND index
        unsigned m0 = um(pk[0], pk[1]), m1 = um(pk[2], pk[3]);
        unsigned m2 = um(pk[4], pk[5]), m3 = um(pk[6], pk[7]);
        unsigned lm = um(um(m0, m1), um(m2, m3));
        unsigned wm = __reduce_min_sync(0xffffffffu, lm);
        if (lane == 0) s_pk[buf][wid] = wm;
        __syncthreads();   // one barrier per iteration (double-buffered)

        // cross-warp min: ONE LDS.128 + 3 IMNMX (depth 2)
        const uint4* q = reinterpret_cast<const uint4*>(s_pk[buf]);
        uint4 a = *q;
        unsigned g = um(um(a.x, a.y), um(a.z, a.w));

        int gj = (int)(g & 1023u);
        total += __uint_as_float(g & PK_MASK);

        float4 pj = pts[gj];   // single broadcast LDS.128

        // mark chosen point visited in its owner's registers (2 fields only)
#pragma unroll
        for (int s = 0; s < PPT; s++) {
            if (gj == tid + s * THREADS) {
                pk[s] = VISITED;
                lx[s] = INF_F;      // poisons dx -> d2 = +inf forever
            }
        }

        // relax
#pragma unroll
        for (int s = 0; s < PPT; s++) {
            float dx = lx[s] - pj.x, dy = ly[s] - pj.y, dz = lz[s] - pj.z;
            float d2 = fmaf(dx, dx, fmaf(dy, dy, dz * dz));
            unsigned cand = (__float_as_uint(d2) & PK_MASK) | (unsigned)(tid + s * THREADS);
            pk[s] = um(pk[s], cand);
        }
    }

    // ---- deterministic finalize in the last-arriving CTA ----
    if (tid == 0) {
        g_partials[prob] = total;
        __threadfence();
        unsigned t = atomicAdd(&g_ticket, 1u);
        s_last = (t == NPROB - 1);
    }
    __syncthreads();
    if (s_last && tid == 0) {
        __threadfence();
        float acc = 0.0f;
#pragma unroll
        for (int p = 0; p < NPROB; p++) acc += g_partials[p];
        out[0] = acc * (1.0f / NPROB);
        g_ticket = 0;   // reset for next graph replay
    }
}

extern "C" void kernel_launch(void* const* d_in, const int* in_sizes, int n_in,
                              void* d_out, int out_size)
{
    const float* r = (const float*)d_in[0];
    float* out = (float*)d_out;
    topo_mst_kernel<<<NPROB, THREADS>>>(r, out);
}

// round 5
// speedup vs baseline: 2.0490x; 1.0055x over previous
#include <cuda_runtime.h>
#include <math.h>

// Dataset-fixed shapes: r is [16, 2048, 3] fp32
#define BATCH   16
#define NCC     2
#define NPTS    1024              // points per MST problem
#define NPROB   (BATCH * NCC)     // 32 independent MST problems
#define THREADS 128               // 4 warps: ONE warp per SMSP (full issue rate)
#define PPT     (NPTS / THREADS)  // 8 points per thread
#define NW      (THREADS / 32)    // 4 warps

__device__ float    g_partials[NPROB];
__device__ unsigned g_ticket;     // zero-init; last CTA resets for graph replay

__device__ __forceinline__ float warp_sum(float v) {
#pragma unroll
    for (int o = 16; o; o >>= 1) v += __shfl_xor_sync(0xffffffffu, v, o);
    return v;
}

__device__ __forceinline__ unsigned um(unsigned a, unsigned b) { return a < b ? a : b; }

// Pack: high 22 bits = float bits of h = d^2/2 (low 10 mantissa bits truncated),
// low 10 bits = point index. Unsigned order == (h, idx) order (h >= 0).
#define PK_MASK 0xFFFFFC00u

__global__ __launch_bounds__(THREADS, 1)
void topo_mst_kernel(const float* __restrict__ r, float* __restrict__ out)
{
    __shared__ float4 pts[NPTS];                    // {x, y, z, q=|p|^2/2}
    __shared__ float redbuf[3][NW];
    __shared__ alignas(16) unsigned s_pk[2][NW];    // double-buffered warp mins
    __shared__ bool s_last;

    const int prob   = blockIdx.x;
    const int sample = prob >> 1;
    const int chunk  = prob & 1;
    const int tid    = threadIdx.x;
    const int lane   = tid & 31;
    const int wid    = tid >> 5;

    const float* base = r + ((size_t)sample * (NCC * NPTS) + (size_t)chunk * NPTS) * 3;

    // ---- Load (thread t owns points t, t+128, ..., t+896) ----
    float lx[PPT], ly[PPT], lz[PPT];
    float sx = 0.f, sy = 0.f, sz = 0.f;
#pragma unroll
    for (int s = 0; s < PPT; s++) {
        int i = tid + s * THREADS;
        float x = base[3 * i + 0];
        float y = base[3 * i + 1];
        float z = base[3 * i + 2];
        lx[s] = x; ly[s] = y; lz[s] = z;
        sx += x; sy += y; sz += z;
    }

    // ---- Mean ----
    sx = warp_sum(sx); sy = warp_sum(sy); sz = warp_sum(sz);
    if (lane == 0) { redbuf[0][wid] = sx; redbuf[1][wid] = sy; redbuf[2][wid] = sz; }
    __syncthreads();
    float mx = 0.f, my = 0.f, mz = 0.f;
#pragma unroll
    for (int w = 0; w < NW; w++) { mx += redbuf[0][w]; my += redbuf[1][w]; mz += redbuf[2][w]; }
    mx *= (1.0f / NPTS); my *= (1.0f / NPTS); mz *= (1.0f / NPTS);
    __syncthreads();

    // ---- Variance ----
    float vx = 0.f, vy = 0.f, vz = 0.f;
#pragma unroll
    for (int s = 0; s < PPT; s++) {
        float dx = lx[s] - mx, dy = ly[s] - my, dz = lz[s] - mz;
        vx = fmaf(dx, dx, vx); vy = fmaf(dy, dy, vy); vz = fmaf(dz, dz, vz);
    }
    vx = warp_sum(vx); vy = warp_sum(vy); vz = warp_sum(vz);
    if (lane == 0) { redbuf[0][wid] = vx; redbuf[1][wid] = vy; redbuf[2][wid] = vz; }
    __syncthreads();
    vx = 0.f; vy = 0.f; vz = 0.f;
#pragma unroll
    for (int w = 0; w < NW; w++) { vx += redbuf[0][w]; vy += redbuf[1][w]; vz += redbuf[2][w]; }
    const float inx = 1.0f / (sqrtf(vx * (1.0f / NPTS)) + 1e-8f);
    const float iny = 1.0f / (sqrtf(vy * (1.0f / NPTS)) + 1e-8f);
    const float inz = 1.0f / (sqrtf(vz * (1.0f / NPTS)) + 1e-8f);

    // ---- Normalize; q = |p|^2/2; shared float4 {x,y,z,q} ----
    float ql[PPT];
#pragma unroll
    for (int s = 0; s < PPT; s++) {
        int i = tid + s * THREADS;
        float x = (lx[s] - mx) * inx;
        float y = (ly[s] - my) * iny;
        float z = (lz[s] - mz) * inz;
        lx[s] = x; ly[s] = y; lz[s] = z;
        ql[s] = 0.5f * fmaf(x, x, fmaf(y, y, z * z));
        pts[i] = make_float4(x, y, z, ql[s]);
    }
    __syncthreads();

    // ---- Prim's MST (h = d^2/2 = q_s + q_j - p.pj) ----
    const float    INF_F   = __int_as_float(0x7f800000);
    const unsigned VISITED = 0xFFFFFFFFu;

    float4 p0 = pts[0];
    unsigned pk[PPT];
#pragma unroll
    for (int s = 0; s < PPT; s++) {
        float h = fmaf(-lx[s], p0.x, fmaf(-ly[s], p0.y, fmaf(-lz[s], p0.z, ql[s] + p0.w)));
        pk[s] = (__float_as_uint(h) & PK_MASK) | (unsigned)(tid + s * THREADS);
    }
    if (tid == 0) {     // root visited: INF q forces its future h = +inf
        pk[0] = VISITED;
        ql[0] = INF_F;
    }

    float total = 0.0f;   // accumulates h (= d^2/2); doubled at the end
    for (int it = 0; it < NPTS - 1; ++it) {
        const int buf = it & 1;

        // thread-local min: 7 IMNMX (depth 3); REDUX carries value AND index
        unsigned m0 = um(pk[0], pk[1]), m1 = um(pk[2], pk[3]);
        unsigned m2 = um(pk[4], pk[5]), m3 = um(pk[6], pk[7]);
        unsigned lm = um(um(m0, m1), um(m2, m3));
        unsigned wm = __reduce_min_sync(0xffffffffu, lm);
        if (lane == 0) s_pk[buf][wid] = wm;
        __syncthreads();   // one barrier per iteration (double-buffered)

        // cross-warp min: ONE LDS.128 + 3 IMNMX (depth 2)
        const uint4* q = reinterpret_cast<const uint4*>(s_pk[buf]);
        uint4 a = *q;
        unsigned g = um(um(a.x, a.y), um(a.z, a.w));

        int gj = (int)(g & 1023u);
        total += __uint_as_float(g & PK_MASK);

        float4 pj = pts[gj];   // single broadcast LDS.128: {x, y, z, q_j}

        // mark chosen point visited in its owner's registers
#pragma unroll
        for (int s = 0; s < PPT; s++) {
            if (gj == tid + s * THREADS) {
                pk[s] = VISITED;
                ql[s] = INF_F;      // h becomes +inf forever (coords stay finite)
            }
        }

        // relax: 6 instr/point (FADD + 3 FFMA + LOP3 + IMNMX)
#pragma unroll
        for (int s = 0; s < PPT; s++) {
            float h = fmaf(-lx[s], pj.x, fmaf(-ly[s], pj.y, fmaf(-lz[s], pj.z, ql[s] + pj.w)));
            unsigned cand = (__float_as_uint(h) & PK_MASK) | (unsigned)(tid + s * THREADS);
            pk[s] = um(pk[s], cand);
        }
    }

    // ---- deterministic finalize in the last-arriving CTA ----
    if (tid == 0) {
        g_partials[prob] = total * 2.0f;   // h -> d^2
        __threadfence();
        unsigned t = atomicAdd(&g_ticket, 1u);
        s_last = (t == NPROB - 1);
    }
    __syncthreads();
    if (s_last && tid == 0) {
        __threadfence();
        float acc = 0.0f;
#pragma unroll
        for (int p = 0; p < NPROB; p++) acc += g_partials[p];
        out[0] = acc * (1.0f / NPROB);
        g_ticket = 0;   // reset for next graph replay
    }
}

extern "C" void kernel_launch(void* const* d_in, const int* in_sizes, int n_in,
                              void* d_out, int out_size)
{
    const float* r = (const float*)d_in[0];
    float* out = (float*)d_out;
    topo_mst_kernel<<<NPROB, THREADS>>>(r, out);
}